// round 6
// baseline (speedup 1.0000x reference)
#include <cuda_runtime.h>
#include <cuda_fp16.h>
#include <math.h>
#include <stdint.h>

#define Bn   256
#define Hn   1024
#define XDn  192
#define YDn  64
#define INn  256
#define PREn 64
#define FWDn 48
#define G4H  4096
#define NCTA 128

// ---------------- scratch (device globals; no allocations allowed) ----------
__device__ __half g_W0h[G4H * 1280], g_W0l[G4H * 1280];
__device__ __half g_W1h[G4H * 2048], g_W1l[G4H * 2048];
__device__ __half g_Wfh[Hn * Hn],    g_Wfl[Hn * Hn];
__device__ float  g_bp0[G4H], g_bp1[G4H];
__device__ __half g_XYh[PREn * Bn * INn], g_XYl[PREn * Bn * INn];
__device__ __half g_FXh[FWDn * Bn * INn], g_FXl[FWDn * Bn * INn];
__device__ __half g_H0h[2][Bn * Hn], g_H0l[2][Bn * Hn];
__device__ __half g_H1h[2][Bn * Hn], g_H1l[2][Bn * Hn];
__device__ float g_c0[Bn * Hn], g_c1[Bn * Hn];
__device__ float g_t1[Bn * Hn], g_t1p[4][Bn * Hn], g_est[Bn * YDn];
__device__ volatile unsigned g_bar_gen;
__device__ unsigned g_bar_cnt;

// ---------------- helpers ----------------------------------------------------
__device__ __forceinline__ float sigf(float x) { return 1.0f / (1.0f + expf(-x)); }

__device__ __forceinline__ void cpa16(void* dst, const void* src) {
    unsigned d = (unsigned)__cvta_generic_to_shared(dst);
    asm volatile("cp.async.cg.shared.global [%0], [%1], 16;\n" :: "r"(d), "l"(src));
}

__device__ __forceinline__ void ldsm_x4(unsigned r[4], const unsigned* p) {
    unsigned addr = (unsigned)__cvta_generic_to_shared(p);
    asm volatile("ldmatrix.sync.aligned.m8n8.x4.shared.b16 {%0,%1,%2,%3}, [%4];\n"
        : "=r"(r[0]), "=r"(r[1]), "=r"(r[2]), "=r"(r[3]) : "r"(addr));
}

__device__ __forceinline__ void mma16816(float c[4], const unsigned a[4], const unsigned b[2]) {
    asm volatile(
        "mma.sync.aligned.m16n8k16.row.col.f32.f16.f16.f32 "
        "{%0,%1,%2,%3}, {%4,%5,%6,%7}, {%8,%9}, {%0,%1,%2,%3};\n"
        : "+f"(c[0]), "+f"(c[1]), "+f"(c[2]), "+f"(c[3])
        : "r"(a[0]), "r"(a[1]), "r"(a[2]), "r"(a[3]), "r"(b[0]), "r"(b[1]));
}

// grid-wide spin barrier (all NCTA CTAs co-resident: 128 < 148 SMs)
__device__ __forceinline__ void gridsync() {
    __syncthreads();
    if (threadIdx.x == 0) {
        __threadfence();
        unsigned gen = g_bar_gen;
        if (atomicAdd(&g_bar_cnt, 1u) == NCTA - 1) {
            atomicExch(&g_bar_cnt, 0u);
            __threadfence();
            g_bar_gen = gen + 1;
        } else {
            while (g_bar_gen == gen) __nanosleep(32);
        }
        __threadfence();
    }
    __syncthreads();
}

// ---------------- fp16x3 GEMM phase (device function) ------------------------
#define BM 64
#define BN 128
#define BK 32
#define RS 20
#define OFF_AH 0
#define OFF_AL (BM * RS)
#define OFF_WH (2 * BM * RS)
#define OFF_WL (2 * BM * RS + BN * RS)
#define STAGE  (2 * BM * RS + 2 * BN * RS)   // 7680 uints
#define NSTG   3
#define SMEMB  (NSTG * STAGE * 4)            // 92160 B

__device__ __forceinline__ void load_tile(
    unsigned* sm, int sbase, int k0, int m0, int n0, int tid,
    const __half* a0h, const __half* a0l, int w0, int lda0,
    const __half* a1h, const __half* a1l, int lda1,
    const __half* wgh, const __half* wgl, int ldw)
{
    const __half *ah, *al; int lda, koff;
    if (k0 < w0) { ah = a0h; al = a0l; lda = lda0; koff = k0; }
    else         { ah = a1h; al = a1l; lda = lda1; koff = k0 - w0; }
#pragma unroll
    for (int i = 0; i < 2; i++) {
        int c = tid + (i << 8);
        int part = c >> 8;
        int row  = (c & 255) >> 2;
        int kc   = c & 3;
        const __half* src = (part ? al : ah) + (size_t)(m0 + row) * lda + koff + kc * 8;
        unsigned* dst = sm + sbase + (part ? OFF_AL : OFF_AH) + row * RS + kc * 4;
        cpa16(dst, src);
    }
#pragma unroll
    for (int i = 0; i < 4; i++) {
        int c = tid + (i << 8);
        int part = c >> 9;
        int row  = (c & 511) >> 2;
        int kc   = c & 3;
        const __half* src = (part ? wgl : wgh) + (size_t)(n0 + row) * ldw + k0 + kc * 8;
        unsigned* dst = sm + sbase + (part ? OFF_WL : OFF_WH) + row * RS + kc * 4;
        cpa16(dst, src);
    }
}

// mode 0: fused LSTM cell (gate-interleaved W); mode 2: raw acc -> out2[r*Hn+c]
__device__ __noinline__ void gemm_phase(
    unsigned* sm, int m0, int n0, int kt0, int NT,
    const __half* a0h, const __half* a0l, int w0, int lda0,
    const __half* a1h, const __half* a1l, int lda1,
    const __half* wgh, const __half* wgl, int ldw,
    const float* bias, int mode,
    float* out2, float* cst, __half* Hh, __half* Hl)
{
    const int tid  = threadIdx.x;
    const int warp = tid >> 5;
    const int lane = tid & 31;
    const int wm = (warp & 1) * 32;
    const int wn = (warp >> 1) * 32;
    const int gr = lane >> 2;
    const int tg = lane & 3;
    const int a_row  = wm + (lane & 15);
    const int a_colu = (lane >> 4) << 2;
    const int b_row  = wn + (lane & 7) + ((lane >> 4) << 3);
    const int b_colu = ((lane >> 3) & 1) << 2;

    float acc[2][4][4];
#pragma unroll
    for (int mi = 0; mi < 2; mi++)
#pragma unroll
        for (int ni = 0; ni < 4; ni++)
#pragma unroll
            for (int e = 0; e < 4; e++) acc[mi][ni][e] = 0.0f;

    load_tile(sm, 0, kt0 * BK, m0, n0, tid, a0h, a0l, w0, lda0, a1h, a1l, lda1, wgh, wgl, ldw);
    asm volatile("cp.async.commit_group;\n");
    if (NT > 1) {
        load_tile(sm, STAGE, (kt0 + 1) * BK, m0, n0, tid, a0h, a0l, w0, lda0, a1h, a1l, lda1, wgh, wgl, ldw);
        asm volatile("cp.async.commit_group;\n");
    }

    for (int i = 0; i < NT; i++) {
        if (i + 2 < NT) {
            load_tile(sm, ((i + 2) % NSTG) * STAGE, (kt0 + i + 2) * BK, m0, n0, tid,
                      a0h, a0l, w0, lda0, a1h, a1l, lda1, wgh, wgl, ldw);
            asm volatile("cp.async.commit_group;\n");
            asm volatile("cp.async.wait_group 2;\n");
        } else if (i + 1 < NT) {
            asm volatile("cp.async.wait_group 1;\n");
        } else {
            asm volatile("cp.async.wait_group 0;\n");
        }
        __syncthreads();

        const unsigned* sb = sm + (i % NSTG) * STAGE;
#pragma unroll
        for (int ks = 0; ks < 2; ks++) {
            const int co = ks * 8;
            unsigned ah[2][4], al[2][4], bh[4][2], bl[4][2];
#pragma unroll
            for (int mi = 0; mi < 2; mi++) {
                ldsm_x4(ah[mi], sb + OFF_AH + (a_row + mi * 16) * RS + co + a_colu);
                ldsm_x4(al[mi], sb + OFF_AL + (a_row + mi * 16) * RS + co + a_colu);
            }
#pragma unroll
            for (int np = 0; np < 2; np++) {
                unsigned th[4], tl[4];
                ldsm_x4(th, sb + OFF_WH + (b_row + np * 16) * RS + co + b_colu);
                ldsm_x4(tl, sb + OFF_WL + (b_row + np * 16) * RS + co + b_colu);
                bh[2*np][0] = th[0]; bh[2*np][1] = th[1];
                bh[2*np+1][0] = th[2]; bh[2*np+1][1] = th[3];
                bl[2*np][0] = tl[0]; bl[2*np][1] = tl[1];
                bl[2*np+1][0] = tl[2]; bl[2*np+1][1] = tl[3];
            }
#pragma unroll
            for (int mi = 0; mi < 2; mi++)
#pragma unroll
                for (int ni = 0; ni < 4; ni++) {
                    mma16816(acc[mi][ni], al[mi], bh[ni]);
                    mma16816(acc[mi][ni], ah[mi], bl[ni]);
                    mma16816(acc[mi][ni], ah[mi], bh[ni]);
                }
        }
        __syncthreads();
    }

    if (mode == 2) {
#pragma unroll
        for (int mi = 0; mi < 2; mi++)
#pragma unroll
            for (int ni = 0; ni < 4; ni++) {
                int row0 = m0 + wm + mi * 16 + gr;
                int col0 = n0 + wn + ni * 8 + tg * 2;
#pragma unroll
                for (int e = 0; e < 4; e++) {
                    int r = row0 + (e >> 1) * 8;
                    int c = col0 + (e & 1);
                    out2[(size_t)r * Hn + c] = acc[mi][ni][e];
                }
            }
    } else {
        // gate-interleaved cell epilogue: cols 4u+{0,1,2,3} = i,f,g,o
#pragma unroll
        for (int mi = 0; mi < 2; mi++)
#pragma unroll
            for (int ni = 0; ni < 4; ni++) {
                int r0 = m0 + wm + mi * 16 + gr;
                int cb = n0 + wn + ni * 8 + tg * 2;
                float v0 = acc[mi][ni][0] + bias[cb];
                float v1 = acc[mi][ni][1] + bias[cb + 1];
                float v2 = acc[mi][ni][2] + bias[cb];
                float v3 = acc[mi][ni][3] + bias[cb + 1];
                float p0 = __shfl_xor_sync(0xffffffffu, v0, 1);
                float p1 = __shfl_xor_sync(0xffffffffu, v1, 1);
                float p2 = __shfl_xor_sync(0xffffffffu, v2, 1);
                float p3 = __shfl_xor_sync(0xffffffffu, v3, 1);
                if (!(tg & 1)) {
                    int u = cb >> 2;
                    int i0 = r0 * Hn + u;
                    float cn = sigf(v1) * cst[i0] + sigf(v0) * tanhf(p0);
                    cst[i0] = cn;
                    float hn = sigf(p1) * tanhf(cn);
                    __half hv = __float2half_rn(hn);
                    Hh[i0] = hv; Hl[i0] = __float2half_rn(hn - __half2float(hv));
                    int i1 = i0 + 8 * Hn;
                    float cn2 = sigf(v3) * cst[i1] + sigf(v2) * tanhf(p2);
                    cst[i1] = cn2;
                    float hn2 = sigf(p3) * tanhf(cn2);
                    __half hv2 = __float2half_rn(hn2);
                    Hh[i1] = hv2; Hl[i1] = __float2half_rn(hn2 - __half2float(hv2));
                }
            }
    }
}

// ---------------- persistent megakernel --------------------------------------
__global__ void __launch_bounds__(256, 1) megakernel(
    const float* __restrict__ pre_y,
    const float* __restrict__ fc_b1,
    const float* __restrict__ fc_w2,
    const float* __restrict__ fc_b2,
    float* __restrict__ outp)
{
    extern __shared__ unsigned sm[];
    const int cta  = blockIdx.x;
    const int tid  = threadIdx.x;
    const int gid  = cta * 256 + tid;

    // ---- init phase ----
    for (int i = gid; i < Bn * Hn; i += NCTA * 256) {
        g_c0[i] = 0.0f; g_c1[i] = 0.0f;
        __half z = __float2half_rn(0.0f);
        g_H0h[0][i] = z; g_H0l[0][i] = z;
        g_H1h[0][i] = z; g_H1l[0][i] = z;
    }
    if (gid < Bn * YDn) g_est[gid] = pre_y[(PREn - 1) * Bn * YDn + gid];
    gridsync();

    const int g_mblk = cta >> 5, g_nblk = cta & 31;        // gate GEMM tile
    int T = 0;

    // ---- encode ----
    for (int t = 0; t < PREn; t++, T++) {
        int rd = T & 1, wr = 1 - rd;
        const __half* xyh = g_XYh + (size_t)t * Bn * INn;
        const __half* xyl = g_XYl + (size_t)t * Bn * INn;
        gemm_phase(sm, g_mblk * BM, g_nblk * BN, 0, 1280 / BK,
                   xyh, xyl, INn, INn, g_H0h[rd], g_H0l[rd], Hn,
                   g_W0h, g_W0l, 1280, g_bp0, 0,
                   nullptr, g_c0, g_H0h[wr], g_H0l[wr]);
        gridsync();
        gemm_phase(sm, g_mblk * BM, g_nblk * BN, 0, 2048 / BK,
                   g_H0h[wr], g_H0l[wr], Hn, Hn, g_H1h[rd], g_H1l[rd], Hn,
                   g_W1h, g_W1l, 2048, g_bp1, 0,
                   nullptr, g_c1, g_H1h[wr], g_H1l[wr]);
        gridsync();
    }

    // ---- decode ----
    for (int t = 0; t < FWDn; t++, T++) {
        int rd = T & 1, wr = 1 - rd;
        __half* fxh = g_FXh + (size_t)t * Bn * INn;
        __half* fxl = g_FXl + (size_t)t * Bn * INn;

        // fc1 split-K x4: 128 work units
        {
            int ks = cta >> 5, rem = cta & 31;
            int mblk = rem >> 3, nblk = rem & 7;
            gemm_phase(sm, mblk * BM, nblk * BN, ks * 8, 8,
                       g_H1h[rd], g_H1l[rd], 1 << 30, Hn, nullptr, nullptr, Hn,
                       g_Wfh, g_Wfl, Hn, nullptr, 2,
                       g_t1p[ks], nullptr, nullptr, nullptr);
        }
        gridsync();

        // t1 combine: tanh(sum of 4 partials + fc_b1)
        for (int i = gid; i < Bn * Hn; i += NCTA * 256) {
            float v = g_t1p[0][i] + g_t1p[1][i] + g_t1p[2][i] + g_t1p[3][i]
                    + fc_b1[i & (Hn - 1)];
            g_t1[i] = tanhf(v);
        }
        gridsync();

        // fc2 + residual est; writes output[t] and est hi/lo into FX[t]
        {
            int gw = cta * 8 + (tid >> 5);
            int lane = tid & 31;
#pragma unroll 1
            for (int oi = 0; oi < 16; oi++) {
                int oidx = gw * 16 + oi;
                int b = oidx >> 6, j = oidx & 63;
                const float* trow = g_t1 + b * Hn;
                const float* wrow = fc_w2 + j * Hn;
                float s = 0.0f;
#pragma unroll 8
                for (int k = lane; k < Hn; k += 32) s += trow[k] * wrow[k];
#pragma unroll
                for (int o = 16; o; o >>= 1) s += __shfl_xor_sync(0xffffffffu, s, o);
                if (lane == 0) {
                    float v = s + fc_b2[j] + g_est[b * YDn + j];
                    g_est[b * YDn + j] = v;
                    outp[(size_t)t * Bn * YDn + b * YDn + j] = v;
                    __half hh = __float2half_rn(v);
                    int d = b * INn + XDn + j;
                    fxh[d] = hh;
                    fxl[d] = __float2half_rn(v - __half2float(hh));
                }
            }
        }
        gridsync();

        gemm_phase(sm, g_mblk * BM, g_nblk * BN, 0, 1280 / BK,
                   fxh, fxl, INn, INn, g_H0h[rd], g_H0l[rd], Hn,
                   g_W0h, g_W0l, 1280, g_bp0, 0,
                   nullptr, g_c0, g_H0h[wr], g_H0l[wr]);
        gridsync();
        gemm_phase(sm, g_mblk * BM, g_nblk * BN, 0, 2048 / BK,
                   g_H0h[wr], g_H0l[wr], Hn, Hn, g_H1h[rd], g_H1l[rd], Hn,
                   g_W1h, g_W1l, 2048, g_bp1, 0,
                   nullptr, g_c1, g_H1h[wr], g_H1l[wr]);
        gridsync();
    }
}

// ---------------- packing kernels (pre-launches) ------------------------------
__global__ void __launch_bounds__(256) split_kernel(
    const float* __restrict__ src, __half* __restrict__ dh, __half* __restrict__ dl,
    int w, int ldd, int off, int total, int remap)
{
    for (int idx = blockIdx.x * 256 + threadIdx.x; idx < total; idx += gridDim.x * 256) {
        int n = idx / w;
        int k = idx - n * w;
        int pr = remap ? (((n & 1023) << 2) | (n >> 10)) : n;
        float v = src[idx];
        __half h = __float2half_rn(v);
        int d = pr * ldd + off + k;
        dh[d] = h;
        dl[d] = __float2half_rn(v - __half2float(h));
    }
}

__global__ void __launch_bounds__(256) biaspack_kernel(
    const float* __restrict__ bi, const float* __restrict__ bh, float* __restrict__ op)
{
    int n = blockIdx.x * 256 + threadIdx.x;
    if (n < G4H) {
        int u = n & 1023, g = n >> 10;
        op[4 * u + g] = bi[n] + bh[n];
    }
}

// ---------------- launch -----------------------------------------------------
extern "C" void kernel_launch(void* const* d_in, const int* in_sizes, int n_in,
                              void* d_out, int out_size)
{
    const float* pre_x  = (const float*)d_in[0];
    const float* pre_y  = (const float*)d_in[1];
    const float* fwd_x  = (const float*)d_in[2];
    const float* w_ih0  = (const float*)d_in[3];
    const float* w_hh0  = (const float*)d_in[4];
    const float* b_ih0  = (const float*)d_in[5];
    const float* b_hh0  = (const float*)d_in[6];
    const float* w_ih1  = (const float*)d_in[7];
    const float* w_hh1  = (const float*)d_in[8];
    const float* b_ih1  = (const float*)d_in[9];
    const float* b_hh1  = (const float*)d_in[10];
    const float* fc_w1  = (const float*)d_in[11];
    const float* fc_b1  = (const float*)d_in[12];
    const float* fc_w2  = (const float*)d_in[13];
    const float* fc_b2  = (const float*)d_in[14];
    float* outp = (float*)d_out;

    cudaFuncSetAttribute(megakernel, cudaFuncAttributeMaxDynamicSharedMemorySize, SMEMB);

    void *pv;
    #define SYM(name, var) cudaGetSymbolAddress(&pv, var); auto* name = (decltype(&var[0]))pv;
    SYM(W0h, g_W0h) SYM(W0l, g_W0l) SYM(W1h, g_W1h) SYM(W1l, g_W1l)
    SYM(Wfh, g_Wfh) SYM(Wfl, g_Wfl) SYM(bp0, g_bp0) SYM(bp1, g_bp1)
    SYM(XYh, g_XYh) SYM(XYl, g_XYl) SYM(FXh, g_FXh) SYM(FXl, g_FXl)
    #undef SYM

    dim3 blk(256);
    int sB = 2048;

    // one-time packing (gate-interleaved weights, hi/lo splits)
    split_kernel<<<sB, blk>>>(w_ih0, W0h, W0l, INn, 1280, 0,   G4H * INn, 1);
    split_kernel<<<sB, blk>>>(w_hh0, W0h, W0l, Hn,  1280, INn, G4H * Hn, 1);
    split_kernel<<<sB, blk>>>(w_ih1, W1h, W1l, Hn,  2048, 0,   G4H * Hn, 1);
    split_kernel<<<sB, blk>>>(w_hh1, W1h, W1l, Hn,  2048, Hn,  G4H * Hn, 1);
    split_kernel<<<sB, blk>>>(fc_w1, Wfh, Wfl, Hn,  1024, 0,   Hn * Hn, 0);
    split_kernel<<<sB, blk>>>(pre_x, XYh, XYl, XDn, INn, 0,    PREn * Bn * XDn, 0);
    split_kernel<<<sB, blk>>>(pre_y, XYh, XYl, YDn, INn, XDn,  PREn * Bn * YDn, 0);
    split_kernel<<<sB, blk>>>(fwd_x, FXh, FXl, XDn, INn, 0,    FWDn * Bn * XDn, 0);
    biaspack_kernel<<<16, blk>>>(b_ih0, b_hh0, bp0);
    biaspack_kernel<<<16, blk>>>(b_ih1, b_hh1, bp1);

    // single persistent kernel for the whole recurrence
    megakernel<<<NCTA, blk, SMEMB>>>(pre_y, fc_b1, fc_w2, fc_b2, outp);
}

// round 7
// speedup vs baseline: 1.2026x; 1.2026x over previous
#include <cuda_runtime.h>
#include <cuda_fp16.h>
#include <math.h>
#include <stdint.h>

#define Bn   256
#define Hn   1024
#define XDn  192
#define YDn  64
#define INn  256
#define PREn 64
#define FWDn 48
#define G4H  4096

// ---------------- scratch (device globals; no allocations allowed) ----------
__device__ __half g_W0h[G4H * 1280], g_W0l[G4H * 1280];
__device__ __half g_W1h[G4H * 2048], g_W1l[G4H * 2048];
__device__ __half g_Wfh[Hn * Hn],    g_Wfl[Hn * Hn];
__device__ float  g_bp0[G4H], g_bp1[G4H];
__device__ __half g_XYh[PREn * Bn * INn], g_XYl[PREn * Bn * INn];
__device__ __half g_FXh[FWDn * Bn * INn], g_FXl[FWDn * Bn * INn];
__device__ __half g_H0h[2][Bn * Hn], g_H0l[2][Bn * Hn];
__device__ __half g_H1h[2][Bn * Hn], g_H1l[2][Bn * Hn];
__device__ float g_c0[Bn * Hn], g_c1[Bn * Hn];
__device__ float g_t1p[4][Bn * Hn], g_est[Bn * YDn];

// ---------------- helpers ----------------------------------------------------
__device__ __forceinline__ float sigf(float x) { return 1.0f / (1.0f + expf(-x)); }

__device__ __forceinline__ void cpa16(void* dst, const void* src) {
    unsigned d = (unsigned)__cvta_generic_to_shared(dst);
    asm volatile("cp.async.cg.shared.global [%0], [%1], 16;\n" :: "r"(d), "l"(src));
}

__device__ __forceinline__ void ldsm_x4(unsigned r[4], const unsigned* p) {
    unsigned addr = (unsigned)__cvta_generic_to_shared(p);
    asm volatile("ldmatrix.sync.aligned.m8n8.x4.shared.b16 {%0,%1,%2,%3}, [%4];\n"
        : "=r"(r[0]), "=r"(r[1]), "=r"(r[2]), "=r"(r[3]) : "r"(addr));
}

__device__ __forceinline__ void mma16816(float c[4], const unsigned a[4], const unsigned b[2]) {
    asm volatile(
        "mma.sync.aligned.m16n8k16.row.col.f32.f16.f16.f32 "
        "{%0,%1,%2,%3}, {%4,%5,%6,%7}, {%8,%9}, {%0,%1,%2,%3};\n"
        : "+f"(c[0]), "+f"(c[1]), "+f"(c[2]), "+f"(c[3])
        : "r"(a[0]), "r"(a[1]), "r"(a[2]), "r"(a[3]), "r"(b[0]), "r"(b[1]));
}

// ---------------- fp16x3 GEMM core (validated in rounds 4/6) -----------------
#define BM 64
#define BN 128
#define BK 32
#define RS 20
#define OFF_AH 0
#define OFF_AL (BM * RS)
#define OFF_WH (2 * BM * RS)
#define OFF_WL (2 * BM * RS + BN * RS)
#define STAGE  (2 * BM * RS + 2 * BN * RS)   // 7680 uints
#define NSTG   3
#define SMEMB  (NSTG * STAGE * 4)            // 92160 B

__device__ __forceinline__ void load_tile(
    unsigned* sm, int sbase, int k0, int m0, int n0, int tid,
    const __half* a0h, const __half* a0l, int w0, int lda0,
    const __half* a1h, const __half* a1l, int lda1,
    const __half* wgh, const __half* wgl, int ldw)
{
    const __half *ah, *al; int lda, koff;
    if (k0 < w0) { ah = a0h; al = a0l; lda = lda0; koff = k0; }
    else         { ah = a1h; al = a1l; lda = lda1; koff = k0 - w0; }
#pragma unroll
    for (int i = 0; i < 2; i++) {
        int c = tid + (i << 8);
        int part = c >> 8;
        int row  = (c & 255) >> 2;
        int kc   = c & 3;
        const __half* src = (part ? al : ah) + (size_t)(m0 + row) * lda + koff + kc * 8;
        unsigned* dst = sm + sbase + (part ? OFF_AL : OFF_AH) + row * RS + kc * 4;
        cpa16(dst, src);
    }
#pragma unroll
    for (int i = 0; i < 4; i++) {
        int c = tid + (i << 8);
        int part = c >> 9;
        int row  = (c & 511) >> 2;
        int kc   = c & 3;
        const __half* src = (part ? wgl : wgh) + (size_t)(n0 + row) * ldw + k0 + kc * 8;
        unsigned* dst = sm + sbase + (part ? OFF_WL : OFF_WH) + row * RS + kc * 4;
        cpa16(dst, src);
    }
}

// mode 0: fused LSTM cell (gate-interleaved W); mode 2: raw acc -> out2[r*Hn+c]
__device__ __forceinline__ void gemm_core(
    unsigned* sm, int m0, int n0, int kt0, int NT,
    const __half* a0h, const __half* a0l, int w0, int lda0,
    const __half* a1h, const __half* a1l, int lda1,
    const __half* wgh, const __half* wgl, int ldw,
    const float* bias, int mode,
    float* out2, float* cst, __half* Hh, __half* Hl)
{
    const int tid  = threadIdx.x;
    const int warp = tid >> 5;
    const int lane = tid & 31;
    const int wm = (warp & 1) * 32;
    const int wn = (warp >> 1) * 32;
    const int gr = lane >> 2;
    const int tg = lane & 3;
    const int a_row  = wm + (lane & 15);
    const int a_colu = (lane >> 4) << 2;
    const int b_row  = wn + (lane & 7) + ((lane >> 4) << 3);
    const int b_colu = ((lane >> 3) & 1) << 2;

    float acc[2][4][4];
#pragma unroll
    for (int mi = 0; mi < 2; mi++)
#pragma unroll
        for (int ni = 0; ni < 4; ni++)
#pragma unroll
            for (int e = 0; e < 4; e++) acc[mi][ni][e] = 0.0f;

    load_tile(sm, 0, kt0 * BK, m0, n0, tid, a0h, a0l, w0, lda0, a1h, a1l, lda1, wgh, wgl, ldw);
    asm volatile("cp.async.commit_group;\n");
    if (NT > 1) {
        load_tile(sm, STAGE, (kt0 + 1) * BK, m0, n0, tid, a0h, a0l, w0, lda0, a1h, a1l, lda1, wgh, wgl, ldw);
        asm volatile("cp.async.commit_group;\n");
    }

    for (int i = 0; i < NT; i++) {
        if (i + 2 < NT) {
            load_tile(sm, ((i + 2) % NSTG) * STAGE, (kt0 + i + 2) * BK, m0, n0, tid,
                      a0h, a0l, w0, lda0, a1h, a1l, lda1, wgh, wgl, ldw);
            asm volatile("cp.async.commit_group;\n");
            asm volatile("cp.async.wait_group 2;\n");
        } else if (i + 1 < NT) {
            asm volatile("cp.async.wait_group 1;\n");
        } else {
            asm volatile("cp.async.wait_group 0;\n");
        }
        __syncthreads();

        const unsigned* sb = sm + (i % NSTG) * STAGE;
#pragma unroll
        for (int ks = 0; ks < 2; ks++) {
            const int co = ks * 8;
            unsigned ah[2][4], al[2][4], bh[4][2], bl[4][2];
#pragma unroll
            for (int mi = 0; mi < 2; mi++) {
                ldsm_x4(ah[mi], sb + OFF_AH + (a_row + mi * 16) * RS + co + a_colu);
                ldsm_x4(al[mi], sb + OFF_AL + (a_row + mi * 16) * RS + co + a_colu);
            }
#pragma unroll
            for (int np = 0; np < 2; np++) {
                unsigned th[4], tl[4];
                ldsm_x4(th, sb + OFF_WH + (b_row + np * 16) * RS + co + b_colu);
                ldsm_x4(tl, sb + OFF_WL + (b_row + np * 16) * RS + co + b_colu);
                bh[2*np][0] = th[0]; bh[2*np][1] = th[1];
                bh[2*np+1][0] = th[2]; bh[2*np+1][1] = th[3];
                bl[2*np][0] = tl[0]; bl[2*np][1] = tl[1];
                bl[2*np+1][0] = tl[2]; bl[2*np+1][1] = tl[3];
            }
#pragma unroll
            for (int mi = 0; mi < 2; mi++)
#pragma unroll
                for (int ni = 0; ni < 4; ni++) {
                    mma16816(acc[mi][ni], al[mi], bh[ni]);
                    mma16816(acc[mi][ni], ah[mi], bl[ni]);
                    mma16816(acc[mi][ni], ah[mi], bh[ni]);
                }
        }
        __syncthreads();
    }

    if (mode == 2) {
#pragma unroll
        for (int mi = 0; mi < 2; mi++)
#pragma unroll
            for (int ni = 0; ni < 4; ni++) {
                int row0 = m0 + wm + mi * 16 + gr;
                int col0 = n0 + wn + ni * 8 + tg * 2;
#pragma unroll
                for (int e = 0; e < 4; e++) {
                    int r = row0 + (e >> 1) * 8;
                    int c = col0 + (e & 1);
                    out2[(size_t)r * Hn + c] = acc[mi][ni][e];
                }
            }
    } else {
        // gate-interleaved cell epilogue: cols 4u+{0,1,2,3} = i,f,g,o
#pragma unroll
        for (int mi = 0; mi < 2; mi++)
#pragma unroll
            for (int ni = 0; ni < 4; ni++) {
                int r0 = m0 + wm + mi * 16 + gr;
                int cb = n0 + wn + ni * 8 + tg * 2;
                float v0 = acc[mi][ni][0] + bias[cb];
                float v1 = acc[mi][ni][1] + bias[cb + 1];
                float v2 = acc[mi][ni][2] + bias[cb];
                float v3 = acc[mi][ni][3] + bias[cb + 1];
                float p0 = __shfl_xor_sync(0xffffffffu, v0, 1);
                float p1 = __shfl_xor_sync(0xffffffffu, v1, 1);
                float p2 = __shfl_xor_sync(0xffffffffu, v2, 1);
                float p3 = __shfl_xor_sync(0xffffffffu, v3, 1);
                if (!(tg & 1)) {
                    int u = cb >> 2;
                    int i0 = r0 * Hn + u;
                    float cn = sigf(v1) * cst[i0] + sigf(v0) * tanhf(p0);
                    cst[i0] = cn;
                    float hn = sigf(p1) * tanhf(cn);
                    __half hv = __float2half_rn(hn);
                    Hh[i0] = hv; Hl[i0] = __float2half_rn(hn - __half2float(hv));
                    int i1 = i0 + 8 * Hn;
                    float cn2 = sigf(v3) * cst[i1] + sigf(v2) * tanhf(p2);
                    cst[i1] = cn2;
                    float hn2 = sigf(p3) * tanhf(cn2);
                    __half hv2 = __float2half_rn(hn2);
                    Hh[i1] = hv2; Hl[i1] = __float2half_rn(hn2 - __half2float(hv2));
                }
            }
    }
}

// ---------------- merged encode step: L1(k-1) on CTAs 0-127, L0(k) on 128-255
// h-state of step s lives in buffer s&1. Initial state ("step -1") in buf 1.
__global__ void __launch_bounds__(256) enc_step(int k)
{
    extern __shared__ unsigned sm[];
    int cta = blockIdx.x;
    if (cta < 128) {
        if (k < 1) return;       // no L1 work at k=0
        int m0 = (cta >> 5) * BM, n0 = (cta & 31) * BN;
        // L1(k-1): A=[h0[(k-1)&1] | h1[(k-2)&1]] -> h1[(k-1)&1], c1
        gemm_core(sm, m0, n0, 0, 2048 / BK,
                  g_H0h[(k + 1) & 1], g_H0l[(k + 1) & 1], Hn, Hn,
                  g_H1h[k & 1], g_H1l[k & 1], Hn,
                  g_W1h, g_W1l, 2048, g_bp1, 0,
                  nullptr, g_c1, g_H1h[(k + 1) & 1], g_H1l[(k + 1) & 1]);
    } else {
        if (k >= PREn) return;   // no L0 work at k=64
        int c2 = cta - 128;
        int m0 = (c2 >> 5) * BM, n0 = (c2 & 31) * BN;
        const __half* xyh = g_XYh + (size_t)k * Bn * INn;
        const __half* xyl = g_XYl + (size_t)k * Bn * INn;
        // L0(k): A=[xy(k) | h0[(k-1)&1]] -> h0[k&1], c0
        gemm_core(sm, m0, n0, 0, 1280 / BK,
                  xyh, xyl, INn, INn,
                  g_H0h[(k + 1) & 1], g_H0l[(k + 1) & 1], Hn,
                  g_W0h, g_W0l, 1280, g_bp0, 0,
                  nullptr, g_c0, g_H0h[k & 1], g_H0l[k & 1]);
    }
}

// ---------------- decode gate GEMMs ------------------------------------------
__global__ void __launch_bounds__(256) dec_l0(int t)
{
    extern __shared__ unsigned sm[];
    int cta = blockIdx.x;
    int m0 = (cta >> 5) * BM, n0 = (cta & 31) * BN;
    int rd = (t + 1) & 1, wr = t & 1;
    const __half* fxh = g_FXh + (size_t)t * Bn * INn;
    const __half* fxl = g_FXl + (size_t)t * Bn * INn;
    gemm_core(sm, m0, n0, 0, 1280 / BK,
              fxh, fxl, INn, INn, g_H0h[rd], g_H0l[rd], Hn,
              g_W0h, g_W0l, 1280, g_bp0, 0,
              nullptr, g_c0, g_H0h[wr], g_H0l[wr]);
}

__global__ void __launch_bounds__(256) dec_l1(int t)
{
    extern __shared__ unsigned sm[];
    int cta = blockIdx.x;
    int m0 = (cta >> 5) * BM, n0 = (cta & 31) * BN;
    int rd = (t + 1) & 1, wr = t & 1;
    gemm_core(sm, m0, n0, 0, 2048 / BK,
              g_H0h[wr], g_H0l[wr], Hn, Hn, g_H1h[rd], g_H1l[rd], Hn,
              g_W1h, g_W1l, 2048, g_bp1, 0,
              nullptr, g_c1, g_H1h[wr], g_H1l[wr]);
}

// ---------------- fc1 split-K x4 (128 CTAs, raw partials) --------------------
__global__ void __launch_bounds__(256) fc1p(int rd)
{
    extern __shared__ unsigned sm[];
    int cta = blockIdx.x;
    int ks = cta >> 5, rem = cta & 31;
    int m0 = ((rem >> 3) & 3) * BM, n0 = (rem & 7) * BN;
    gemm_core(sm, m0, n0, ks * 8, 8,
              g_H1h[rd], g_H1l[rd], 1 << 30, Hn, nullptr, nullptr, Hn,
              g_Wfh, g_Wfl, Hn, nullptr, 2,
              g_t1p[ks], nullptr, nullptr, nullptr);
}

// ---------------- fc combine + tanh + fc2 + residual est ---------------------
__global__ void __launch_bounds__(256) fccomb(
    const float* __restrict__ fc_b1, const float* __restrict__ fc_w2,
    const float* __restrict__ fc_b2, float* __restrict__ outp_t,
    __half* __restrict__ fxh, __half* __restrict__ fxl)
{
    __shared__ float t1row[Hn];
    int b = blockIdx.x;
    for (int i = threadIdx.x; i < Hn; i += 256) {
        int idx = b * Hn + i;
        float v = g_t1p[0][idx] + g_t1p[1][idx] + g_t1p[2][idx] + g_t1p[3][idx]
                + fc_b1[i];
        t1row[i] = tanhf(v);
    }
    __syncthreads();
    int w = threadIdx.x >> 5, lane = threadIdx.x & 31;
#pragma unroll 1
    for (int jj = 0; jj < 8; jj++) {
        int j = w * 8 + jj;
        const float* wrow = fc_w2 + (size_t)j * Hn;
        float s = 0.0f;
#pragma unroll 8
        for (int k = lane; k < Hn; k += 32) s += t1row[k] * wrow[k];
#pragma unroll
        for (int o = 16; o; o >>= 1) s += __shfl_xor_sync(0xffffffffu, s, o);
        if (lane == 0) {
            float v = s + fc_b2[j] + g_est[b * YDn + j];
            g_est[b * YDn + j] = v;
            outp_t[b * YDn + j] = v;
            __half hh = __float2half_rn(v);
            int d = b * INn + XDn + j;
            fxh[d] = hh;
            fxl[d] = __float2half_rn(v - __half2float(hh));
        }
    }
}

// ---------------- packing kernels --------------------------------------------
__global__ void __launch_bounds__(256) split_kernel(
    const float* __restrict__ src, __half* __restrict__ dh, __half* __restrict__ dl,
    int w, int ldd, int off, int total, int remap)
{
    for (int idx = blockIdx.x * 256 + threadIdx.x; idx < total; idx += gridDim.x * 256) {
        int n = idx / w;
        int k = idx - n * w;
        int pr = remap ? (((n & 1023) << 2) | (n >> 10)) : n;
        float v = src[idx];
        __half h = __float2half_rn(v);
        int d = pr * ldd + off + k;
        dh[d] = h;
        dl[d] = __float2half_rn(v - __half2float(h));
    }
}

__global__ void __launch_bounds__(256) biaspack_kernel(
    const float* __restrict__ bi, const float* __restrict__ bh, float* __restrict__ op)
{
    int n = blockIdx.x * 256 + threadIdx.x;
    if (n < G4H) {
        int u = n & 1023, g = n >> 10;
        op[4 * u + g] = bi[n] + bh[n];
    }
}

// init: zero state buffers (buf 1 = "step -1"), est = pre_y[-1]
__global__ void __launch_bounds__(256) init_kernel(const float* __restrict__ pre_y)
{
    int i = blockIdx.x * 256 + threadIdx.x;
    if (i < Bn * Hn) {
        g_c0[i] = 0.0f; g_c1[i] = 0.0f;
        __half z = __float2half_rn(0.0f);
        g_H0h[1][i] = z; g_H0l[1][i] = z;
        g_H1h[1][i] = z; g_H1l[1][i] = z;
    }
    if (i < Bn * YDn) g_est[i] = pre_y[(PREn - 1) * Bn * YDn + i];
}

// ---------------- launch -----------------------------------------------------
extern "C" void kernel_launch(void* const* d_in, const int* in_sizes, int n_in,
                              void* d_out, int out_size)
{
    const float* pre_x  = (const float*)d_in[0];
    const float* pre_y  = (const float*)d_in[1];
    const float* fwd_x  = (const float*)d_in[2];
    const float* w_ih0  = (const float*)d_in[3];
    const float* w_hh0  = (const float*)d_in[4];
    const float* b_ih0  = (const float*)d_in[5];
    const float* b_hh0  = (const float*)d_in[6];
    const float* w_ih1  = (const float*)d_in[7];
    const float* w_hh1  = (const float*)d_in[8];
    const float* b_ih1  = (const float*)d_in[9];
    const float* b_hh1  = (const float*)d_in[10];
    const float* fc_w1  = (const float*)d_in[11];
    const float* fc_b1  = (const float*)d_in[12];
    const float* fc_w2  = (const float*)d_in[13];
    const float* fc_b2  = (const float*)d_in[14];
    float* outp = (float*)d_out;

    cudaFuncSetAttribute(enc_step, cudaFuncAttributeMaxDynamicSharedMemorySize, SMEMB);
    cudaFuncSetAttribute(dec_l0,   cudaFuncAttributeMaxDynamicSharedMemorySize, SMEMB);
    cudaFuncSetAttribute(dec_l1,   cudaFuncAttributeMaxDynamicSharedMemorySize, SMEMB);
    cudaFuncSetAttribute(fc1p,     cudaFuncAttributeMaxDynamicSharedMemorySize, SMEMB);

    void *pv;
    #define SYM(name, var) cudaGetSymbolAddress(&pv, var); auto* name = (decltype(&var[0]))pv;
    SYM(W0h, g_W0h) SYM(W0l, g_W0l) SYM(W1h, g_W1h) SYM(W1l, g_W1l)
    SYM(Wfh, g_Wfh) SYM(Wfl, g_Wfl) SYM(bp0, g_bp0) SYM(bp1, g_bp1)
    SYM(XYh, g_XYh) SYM(XYl, g_XYl) SYM(FXh, g_FXh) SYM(FXl, g_FXl)
    #undef SYM

    dim3 blk(256);
    int sB = 2048;

    // one-time packing (gate-interleaved weights, hi/lo splits)
    split_kernel<<<sB, blk>>>(w_ih0, W0h, W0l, INn, 1280, 0,   G4H * INn, 1);
    split_kernel<<<sB, blk>>>(w_hh0, W0h, W0l, Hn,  1280, INn, G4H * Hn, 1);
    split_kernel<<<sB, blk>>>(w_ih1, W1h, W1l, Hn,  2048, 0,   G4H * Hn, 1);
    split_kernel<<<sB, blk>>>(w_hh1, W1h, W1l, Hn,  2048, Hn,  G4H * Hn, 1);
    split_kernel<<<sB, blk>>>(fc_w1, Wfh, Wfl, Hn,  1024, 0,   Hn * Hn, 0);
    split_kernel<<<sB, blk>>>(pre_x, XYh, XYl, XDn, INn, 0,    PREn * Bn * XDn, 0);
    split_kernel<<<sB, blk>>>(pre_y, XYh, XYl, YDn, INn, XDn,  PREn * Bn * YDn, 0);
    split_kernel<<<sB, blk>>>(fwd_x, FXh, FXl, XDn, INn, 0,    FWDn * Bn * XDn, 0);
    biaspack_kernel<<<16, blk>>>(b_ih0, b_hh0, bp0);
    biaspack_kernel<<<16, blk>>>(b_ih1, b_hh1, bp1);
    init_kernel<<<(Bn * Hn) / 256, blk>>>(pre_y);

    // ---------------- encode: merged L0(k) || L1(k-1), k = 0..PREn ----------
    for (int k = 0; k <= PREn; k++)
        enc_step<<<256, blk, SMEMB>>>(k);

    // ---------------- decode ------------------------------------------------
    // after encode: h0 in buf[63&1]=1, h1 in buf 1; decode step t: rd=(t+1)&1
    for (int t = 0; t < FWDn; t++) {
        int rd = (t + 1) & 1;
        __half* fxh = FXh + (size_t)t * Bn * INn;
        __half* fxl = FXl + (size_t)t * Bn * INn;
        fc1p<<<128, blk, SMEMB>>>(rd);
        fccomb<<<256, blk>>>(fc_b1, fc_w2, fc_b2,
                             outp + (size_t)t * Bn * YDn, fxh, fxl);
        dec_l0<<<128, blk, SMEMB>>>(t);
        dec_l1<<<128, blk, SMEMB>>>(t);
    }
}